// round 9
// baseline (speedup 1.0000x reference)
#include <cuda_runtime.h>
#include <cfloat>
#include <cstdint>

// ----------------------------------------------------------------------------
// GnnSynthetic: 3-layer GCN forward, N=50000 nodes, E=800000 edges, dims 64.
// Output layout (fp32): [node_embeddings N x 192][graph_embedding 192][logits 4]
//
// Hard rules learned:
//   R4/R5: no atomics into d_in/d_out (host-coherent buffers trap, err 717).
//   R6:    integer inputs are int32 on device.
//   R7:    single-block scan was 70us (30% of runtime) -> multi-block 3-pass scan.
// ----------------------------------------------------------------------------

#define MAXN 50000
#define MAXE 800000
#define SCAN_CHUNK 1024   // elements per block in the scan passes

__device__ __align__(16) float g_h[(size_t)MAXN * 64];  // GEMM result h = X @ W
__device__ float g_dinv[MAXN];             // rsqrt(deg)
__device__ __align__(16) int g_cnt[MAXN];  // histogram / fill cursor
__device__ __align__(16) int g_off[MAXN + 4]; // CSR row offsets (by dst)
__device__ int   g_src[MAXE];              // CSR column indices (src node)
__device__ float g_nrm[MAXE];              // per-edge norm dinv[src]*dinv[dst]
__device__ float g_gmax[192];              // graph-max accumulator (device-local)
__device__ int   g_bsum[256];              // scan block partials

// ---------------- helpers ----------------

__device__ __forceinline__ void atomicMaxFloat(float* addr, float v) {
    if (v >= 0.0f) atomicMax((int*)addr, __float_as_int(v));
    else           atomicMin((unsigned int*)addr, __float_as_uint(v));
}

// ---------------- CSR build ----------------

__global__ void k_zero(int n) {
    int i = blockIdx.x * blockDim.x + threadIdx.x;
    if (i < n)   g_cnt[i] = 0;
    if (i < 192) g_gmax[i] = -FLT_MAX;
}

__global__ void k_hist(const int* __restrict__ dstA, int E) {
    int e = blockIdx.x * blockDim.x + threadIdx.x;
    if (e < E) atomicAdd(&g_cnt[dstA[e]], 1);
}

// ---- scan pass 1: per-block local exclusive scan (coalesced int4) + dinv ----
// 256 threads, 4 elements/thread, SCAN_CHUNK per block.
__global__ void k_scan1(int n) {
    __shared__ int warpsum[8];
    int tid  = threadIdx.x;
    int lane = tid & 31, wid = tid >> 5;
    int idx  = blockIdx.x * SCAN_CHUNK + tid * 4;

    int4 v = make_int4(0, 0, 0, 0);
    if (idx + 3 < n) {
        v = *(const int4*)(g_cnt + idx);
    } else {
        if (idx + 0 < n) v.x = g_cnt[idx + 0];
        if (idx + 1 < n) v.y = g_cnt[idx + 1];
        if (idx + 2 < n) v.z = g_cnt[idx + 2];
        if (idx + 3 < n) v.w = g_cnt[idx + 3];
    }
    int s = v.x + v.y + v.z + v.w;

    // fold in dinv computation (reads v anyway)
    if (idx + 0 < n) g_dinv[idx + 0] = rsqrtf((float)v.x + 1.0f);
    if (idx + 1 < n) g_dinv[idx + 1] = rsqrtf((float)v.y + 1.0f);
    if (idx + 2 < n) g_dinv[idx + 2] = rsqrtf((float)v.z + 1.0f);
    if (idx + 3 < n) g_dinv[idx + 3] = rsqrtf((float)v.w + 1.0f);

    // warp inclusive scan of s
    int p = s;
    #pragma unroll
    for (int o = 1; o < 32; o <<= 1) {
        int t = __shfl_up_sync(0xFFFFFFFF, p, o);
        if (lane >= o) p += t;
    }
    if (lane == 31) warpsum[wid] = p;
    __syncthreads();
    if (wid == 0) {
        int ws = (lane < 8) ? warpsum[lane] : 0;
        #pragma unroll
        for (int o = 1; o < 8; o <<= 1) {
            int t = __shfl_up_sync(0xFFFFFFFF, ws, o);
            if (lane >= o) ws += t;
        }
        if (lane < 8) warpsum[lane] = ws;
    }
    __syncthreads();

    int excl = ((wid > 0) ? warpsum[wid - 1] : 0) + (p - s);  // thread's exclusive start
    int run = excl;
    if (idx + 0 < n) { g_off[idx + 0] = run; run += v.x; }
    if (idx + 1 < n) { g_off[idx + 1] = run; run += v.y; }
    if (idx + 2 < n) { g_off[idx + 2] = run; run += v.z; }
    if (idx + 3 < n) { g_off[idx + 3] = run; }

    if (tid == 0) g_bsum[blockIdx.x] = warpsum[7];  // block total
}

// ---- scan pass 2: exclusive scan of block partials (single small block) ----
__global__ void k_scan2(int nb) {
    __shared__ int sh[256];
    int tid = threadIdx.x;
    int v = (tid < nb) ? g_bsum[tid] : 0;
    sh[tid] = v;
    __syncthreads();
    #pragma unroll
    for (int o = 1; o < 256; o <<= 1) {
        int t = (tid >= o) ? sh[tid - o] : 0;
        __syncthreads();
        sh[tid] += t;
        __syncthreads();
    }
    if (tid < nb) g_bsum[tid] = sh[tid] - v;  // exclusive
}

// ---- scan pass 3: add block prefix, reset cursor, cap total ----
__global__ void k_scan3(int n, int E) {
    int tid = threadIdx.x;
    int idx = blockIdx.x * SCAN_CHUNK + tid * 4;
    int add = g_bsum[blockIdx.x];
    #pragma unroll
    for (int k = 0; k < 4; k++) {
        int i = idx + k;
        if (i < n) { g_off[i] += add; g_cnt[i] = 0; }
    }
    if (blockIdx.x == 0 && tid == 0) g_off[n] = E;
}

__global__ void k_fill(const int* __restrict__ srcA,
                       const int* __restrict__ dstA, int E) {
    int e = blockIdx.x * blockDim.x + threadIdx.x;
    if (e >= E) return;
    int s = srcA[e];
    int d = dstA[e];
    int pos = atomicAdd(&g_cnt[d], 1);
    int idx = g_off[d] + pos;
    g_src[idx] = s;
    g_nrm[idx] = g_dinv[s] * g_dinv[d];
}

// ---------------- GEMM: g_h[N,64] = X[N,64(ldx)] @ W[64,64] ----------------

__global__ void k_gemm64(const float* __restrict__ X, int ldx,
                         const float* __restrict__ W, int nrows) {
    __shared__ float As[64][65];
    __shared__ float Ws[64][64];

    int tid  = threadIdx.x;
    int row0 = blockIdx.x * 64;

    {
        const float4* W4 = (const float4*)W;
        float4* Ws4 = (float4*)Ws;
        #pragma unroll
        for (int i = tid; i < 1024; i += 256) Ws4[i] = W4[i];
    }
    #pragma unroll
    for (int i = tid; i < 1024; i += 256) {
        int r = i >> 4, c4 = i & 15;
        int grow = row0 + r;
        float4 v = make_float4(0.f, 0.f, 0.f, 0.f);
        if (grow < nrows) v = *(const float4*)(X + (size_t)grow * ldx + c4 * 4);
        As[r][c4 * 4 + 0] = v.x;
        As[r][c4 * 4 + 1] = v.y;
        As[r][c4 * 4 + 2] = v.z;
        As[r][c4 * 4 + 3] = v.w;
    }
    __syncthreads();

    int tx = tid & 15, ty = tid >> 4;
    float acc[4][4];
    #pragma unroll
    for (int i = 0; i < 4; i++)
        #pragma unroll
        for (int j = 0; j < 4; j++) acc[i][j] = 0.f;

    #pragma unroll
    for (int k = 0; k < 64; k++) {
        float4 b = *(const float4*)(&Ws[k][tx * 4]);
        #pragma unroll
        for (int i = 0; i < 4; i++) {
            float a = As[ty * 4 + i][k];
            acc[i][0] += a * b.x;
            acc[i][1] += a * b.y;
            acc[i][2] += a * b.z;
            acc[i][3] += a * b.w;
        }
    }

    #pragma unroll
    for (int i = 0; i < 4; i++) {
        int grow = row0 + ty * 4 + i;
        if (grow < nrows)
            *(float4*)(g_h + (size_t)grow * 64 + tx * 4) =
                make_float4(acc[i][0], acc[i][1], acc[i][2], acc[i][3]);
    }
}

// ---------------- gather: warp per node (plain stores into d_out) ----------

__global__ void k_gather(const float* __restrict__ bias,
                         float* __restrict__ out, int n, int offc, int do_relu) {
    int node = (blockIdx.x * blockDim.x + threadIdx.x) >> 5;
    if (node >= n) return;
    int lane = threadIdx.x & 31;

    int beg = g_off[node];
    int end = g_off[node + 1];
    float di = g_dinv[node];
    float self = di * di;

    const float2* hb = (const float2*)g_h;
    float2 acc = ((const float2*)bias)[lane];
    float2 hs = hb[(size_t)node * 32 + lane];
    acc.x += hs.x * self;
    acc.y += hs.y * self;

    int j = beg;
    for (; j + 1 < end; j += 2) {
        int   s0 = g_src[j],     s1 = g_src[j + 1];
        float w0 = g_nrm[j],     w1 = g_nrm[j + 1];
        float2 h0 = hb[(size_t)s0 * 32 + lane];
        float2 h1 = hb[(size_t)s1 * 32 + lane];
        acc.x += h0.x * w0; acc.y += h0.y * w0;
        acc.x += h1.x * w1; acc.y += h1.y * w1;
    }
    if (j < end) {
        int   s0 = g_src[j];
        float w0 = g_nrm[j];
        float2 h0 = hb[(size_t)s0 * 32 + lane];
        acc.x += h0.x * w0; acc.y += h0.y * w0;
    }

    if (do_relu) {
        acc.x = fmaxf(acc.x, 0.f);
        acc.y = fmaxf(acc.y, 0.f);
    }
    ((float2*)(out + (size_t)node * 192 + offc))[lane] = acc;
}

// ---------------- graph embedding: columnwise max into DEVICE scratch ------

__global__ void k_gmax(const float* __restrict__ ne, int n) {
    int j = threadIdx.x;  // 0..191
    float m = -FLT_MAX;
    for (int i = blockIdx.x; i < n; i += gridDim.x)
        m = fmaxf(m, ne[(size_t)i * 192 + j]);
    atomicMaxFloat(&g_gmax[j], m);
}

// ---------------- finalize: copy gmax + target logits (plain stores) -------

__global__ void k_final(const float* __restrict__ ne,
                        const float* __restrict__ fcW,
                        const float* __restrict__ fcb,
                        const int* __restrict__ tgt,
                        float* __restrict__ outtail) {
    int tid = threadIdx.x;  // 192 threads
    outtail[tid] = g_gmax[tid];

    if (tid < 32) {
        int t = tgt[0];
        const float* row = ne + (size_t)t * 192;
        float s0 = 0.f, s1 = 0.f, s2 = 0.f, s3 = 0.f;
        for (int k = tid; k < 192; k += 32) {
            float e = row[k];
            s0 += e * fcW[k * 4 + 0];
            s1 += e * fcW[k * 4 + 1];
            s2 += e * fcW[k * 4 + 2];
            s3 += e * fcW[k * 4 + 3];
        }
        #pragma unroll
        for (int o = 16; o > 0; o >>= 1) {
            s0 += __shfl_down_sync(0xFFFFFFFF, s0, o);
            s1 += __shfl_down_sync(0xFFFFFFFF, s1, o);
            s2 += __shfl_down_sync(0xFFFFFFFF, s2, o);
            s3 += __shfl_down_sync(0xFFFFFFFF, s3, o);
        }
        if (tid == 0) {
            outtail[192 + 0] = s0 + fcb[0];
            outtail[192 + 1] = s1 + fcb[1];
            outtail[192 + 2] = s2 + fcb[2];
            outtail[192 + 3] = s3 + fcb[3];
        }
    }
}

// ---------------- launch ----------------

extern "C" void kernel_launch(void* const* d_in, const int* in_sizes, int n_in,
                              void* d_out, int out_size) {
    const float* x   = (const float*)d_in[0];
    const int*   ei  = (const int*)d_in[1];
    // d_in[2] = batch (unused)
    const int*   tgt = (const int*)d_in[3];
    const float* W1  = (const float*)d_in[4];
    const float* b1  = (const float*)d_in[5];
    const float* W2  = (const float*)d_in[6];
    const float* b2  = (const float*)d_in[7];
    const float* W3  = (const float*)d_in[8];
    const float* b3  = (const float*)d_in[9];
    const float* fcW = (const float*)d_in[10];
    const float* fcb = (const float*)d_in[11];

    float* out = (float*)d_out;

    const int n = in_sizes[0] / 64;   // 50000
    const int E = in_sizes[1] / 2;    // 800000

    const int* srcA = ei;             // edge_index[0]
    const int* dstA = ei + E;         // edge_index[1]

    float* ne = out;                  // [n,192]

    const int B = 256;
    const int nBlkN  = (n + B - 1) / B;
    const int nBlkE  = (E + B - 1) / B;
    const int nBlkG  = (n + 63) / 64;
    const int nBlkW  = (n * 32 + B - 1) / B;          // warp-per-node gather
    const int nChunk = (n + SCAN_CHUNK - 1) / SCAN_CHUNK;  // 49 scan blocks

    // ---- CSR build (shared by all 3 layers) ----
    k_zero<<<nBlkN, B>>>(n);
    k_hist<<<nBlkE, B>>>(dstA, E);
    k_scan1<<<nChunk, B>>>(n);       // local scan + dinv
    k_scan2<<<1, 256>>>(nChunk);     // scan block partials
    k_scan3<<<nChunk, B>>>(n, E);    // propagate + reset cursor
    k_fill<<<nBlkE, B>>>(srcA, dstA, E);

    // ---- layer 1: x (ld 64) -> cols [0,64), relu ----
    k_gemm64<<<nBlkG, B>>>(x, 64, W1, n);
    k_gather<<<nBlkW, B>>>(b1, ne, n, 0, 1);

    // ---- layer 2: x1 = ne[:,0:64) (ld 192) -> cols [64,128), relu ----
    k_gemm64<<<nBlkG, B>>>(ne, 192, W2, n);
    k_gather<<<nBlkW, B>>>(b2, ne, n, 64, 1);

    // ---- layer 3: x2 = ne[:,64:128) (ld 192) -> cols [128,192), no relu ----
    k_gemm64<<<nBlkG, B>>>(ne + 64, 192, W3, n);
    k_gather<<<nBlkW, B>>>(b3, ne, n, 128, 0);

    // ---- graph embedding (device scratch) + tail write ----
    k_gmax<<<512, 192>>>(ne, n);
    k_final<<<1, 192>>>(ne, fcW, fcb, tgt, out + (size_t)n * 192);
}

// round 10
// speedup vs baseline: 1.0067x; 1.0067x over previous
#include <cuda_runtime.h>
#include <cfloat>
#include <cstdint>

// ----------------------------------------------------------------------------
// GnnSynthetic: 3-layer GCN forward, N=50000 nodes, E=800000 edges, dims 64.
// Output layout (fp32): [node_embeddings N x 192][graph_embedding 192][logits 4]
//
// Hard rules learned:
//   R4/R5: no atomics into d_in/d_out (host-coherent buffers trap, err 717).
//   R6:    integer inputs are int32 on device.
//   R7:    single-block scan was 70us (30% of runtime) -> multi-block 3-pass scan.
// ----------------------------------------------------------------------------

#define MAXN 50000
#define MAXE 800000
#define SCAN_CHUNK 1024   // elements per block in the scan passes

__device__ __align__(16) float g_h[(size_t)MAXN * 64];  // GEMM result h = X @ W
__device__ float g_dinv[MAXN];             // rsqrt(deg)
__device__ __align__(16) int g_cnt[MAXN];  // histogram / fill cursor
__device__ __align__(16) int g_off[MAXN + 4]; // CSR row offsets (by dst)
__device__ int   g_src[MAXE];              // CSR column indices (src node)
__device__ float g_nrm[MAXE];              // per-edge norm dinv[src]*dinv[dst]
__device__ float g_gmax[192];              // graph-max accumulator (device-local)
__device__ int   g_bsum[256];              // scan block partials

// ---------------- helpers ----------------

__device__ __forceinline__ void atomicMaxFloat(float* addr, float v) {
    if (v >= 0.0f) atomicMax((int*)addr, __float_as_int(v));
    else           atomicMin((unsigned int*)addr, __float_as_uint(v));
}

// ---------------- CSR build ----------------

__global__ void k_zero(int n) {
    int i = blockIdx.x * blockDim.x + threadIdx.x;
    if (i < n)   g_cnt[i] = 0;
    if (i < 192) g_gmax[i] = -FLT_MAX;
}

__global__ void k_hist(const int* __restrict__ dstA, int E) {
    int e = blockIdx.x * blockDim.x + threadIdx.x;
    if (e < E) atomicAdd(&g_cnt[dstA[e]], 1);
}

// ---- scan pass 1: per-block local exclusive scan (coalesced int4) + dinv ----
// 256 threads, 4 elements/thread, SCAN_CHUNK per block.
__global__ void k_scan1(int n) {
    __shared__ int warpsum[8];
    int tid  = threadIdx.x;
    int lane = tid & 31, wid = tid >> 5;
    int idx  = blockIdx.x * SCAN_CHUNK + tid * 4;

    int4 v = make_int4(0, 0, 0, 0);
    if (idx + 3 < n) {
        v = *(const int4*)(g_cnt + idx);
    } else {
        if (idx + 0 < n) v.x = g_cnt[idx + 0];
        if (idx + 1 < n) v.y = g_cnt[idx + 1];
        if (idx + 2 < n) v.z = g_cnt[idx + 2];
        if (idx + 3 < n) v.w = g_cnt[idx + 3];
    }
    int s = v.x + v.y + v.z + v.w;

    // fold in dinv computation (reads v anyway)
    if (idx + 0 < n) g_dinv[idx + 0] = rsqrtf((float)v.x + 1.0f);
    if (idx + 1 < n) g_dinv[idx + 1] = rsqrtf((float)v.y + 1.0f);
    if (idx + 2 < n) g_dinv[idx + 2] = rsqrtf((float)v.z + 1.0f);
    if (idx + 3 < n) g_dinv[idx + 3] = rsqrtf((float)v.w + 1.0f);

    // warp inclusive scan of s
    int p = s;
    #pragma unroll
    for (int o = 1; o < 32; o <<= 1) {
        int t = __shfl_up_sync(0xFFFFFFFF, p, o);
        if (lane >= o) p += t;
    }
    if (lane == 31) warpsum[wid] = p;
    __syncthreads();
    if (wid == 0) {
        int ws = (lane < 8) ? warpsum[lane] : 0;
        #pragma unroll
        for (int o = 1; o < 8; o <<= 1) {
            int t = __shfl_up_sync(0xFFFFFFFF, ws, o);
            if (lane >= o) ws += t;
        }
        if (lane < 8) warpsum[lane] = ws;
    }
    __syncthreads();

    int excl = ((wid > 0) ? warpsum[wid - 1] : 0) + (p - s);  // thread's exclusive start
    int run = excl;
    if (idx + 0 < n) { g_off[idx + 0] = run; run += v.x; }
    if (idx + 1 < n) { g_off[idx + 1] = run; run += v.y; }
    if (idx + 2 < n) { g_off[idx + 2] = run; run += v.z; }
    if (idx + 3 < n) { g_off[idx + 3] = run; }

    if (tid == 0) g_bsum[blockIdx.x] = warpsum[7];  // block total
}

// ---- scan pass 2: exclusive scan of block partials (single small block) ----
__global__ void k_scan2(int nb) {
    __shared__ int sh[256];
    int tid = threadIdx.x;
    int v = (tid < nb) ? g_bsum[tid] : 0;
    sh[tid] = v;
    __syncthreads();
    #pragma unroll
    for (int o = 1; o < 256; o <<= 1) {
        int t = (tid >= o) ? sh[tid - o] : 0;
        __syncthreads();
        sh[tid] += t;
        __syncthreads();
    }
    if (tid < nb) g_bsum[tid] = sh[tid] - v;  // exclusive
}

// ---- scan pass 3: add block prefix, reset cursor, cap total ----
__global__ void k_scan3(int n, int E) {
    int tid = threadIdx.x;
    int idx = blockIdx.x * SCAN_CHUNK + tid * 4;
    int add = g_bsum[blockIdx.x];
    #pragma unroll
    for (int k = 0; k < 4; k++) {
        int i = idx + k;
        if (i < n) { g_off[i] += add; g_cnt[i] = 0; }
    }
    if (blockIdx.x == 0 && tid == 0) g_off[n] = E;
}

__global__ void k_fill(const int* __restrict__ srcA,
                       const int* __restrict__ dstA, int E) {
    int e = blockIdx.x * blockDim.x + threadIdx.x;
    if (e >= E) return;
    int s = srcA[e];
    int d = dstA[e];
    int pos = atomicAdd(&g_cnt[d], 1);
    int idx = g_off[d] + pos;
    g_src[idx] = s;
    g_nrm[idx] = g_dinv[s] * g_dinv[d];
}

// ---------------- GEMM: g_h[N,64] = X[N,64(ldx)] @ W[64,64] ----------------

__global__ void k_gemm64(const float* __restrict__ X, int ldx,
                         const float* __restrict__ W, int nrows) {
    __shared__ float As[64][65];
    __shared__ float Ws[64][64];

    int tid  = threadIdx.x;
    int row0 = blockIdx.x * 64;

    {
        const float4* W4 = (const float4*)W;
        float4* Ws4 = (float4*)Ws;
        #pragma unroll
        for (int i = tid; i < 1024; i += 256) Ws4[i] = W4[i];
    }
    #pragma unroll
    for (int i = tid; i < 1024; i += 256) {
        int r = i >> 4, c4 = i & 15;
        int grow = row0 + r;
        float4 v = make_float4(0.f, 0.f, 0.f, 0.f);
        if (grow < nrows) v = *(const float4*)(X + (size_t)grow * ldx + c4 * 4);
        As[r][c4 * 4 + 0] = v.x;
        As[r][c4 * 4 + 1] = v.y;
        As[r][c4 * 4 + 2] = v.z;
        As[r][c4 * 4 + 3] = v.w;
    }
    __syncthreads();

    int tx = tid & 15, ty = tid >> 4;
    float acc[4][4];
    #pragma unroll
    for (int i = 0; i < 4; i++)
        #pragma unroll
        for (int j = 0; j < 4; j++) acc[i][j] = 0.f;

    #pragma unroll
    for (int k = 0; k < 64; k++) {
        float4 b = *(const float4*)(&Ws[k][tx * 4]);
        #pragma unroll
        for (int i = 0; i < 4; i++) {
            float a = As[ty * 4 + i][k];
            acc[i][0] += a * b.x;
            acc[i][1] += a * b.y;
            acc[i][2] += a * b.z;
            acc[i][3] += a * b.w;
        }
    }

    #pragma unroll
    for (int i = 0; i < 4; i++) {
        int grow = row0 + ty * 4 + i;
        if (grow < nrows)
            *(float4*)(g_h + (size_t)grow * 64 + tx * 4) =
                make_float4(acc[i][0], acc[i][1], acc[i][2], acc[i][3]);
    }
}

// ---------------- gather: warp per node (plain stores into d_out) ----------

__global__ void k_gather(const float* __restrict__ bias,
                         float* __restrict__ out, int n, int offc, int do_relu) {
    int node = (blockIdx.x * blockDim.x + threadIdx.x) >> 5;
    if (node >= n) return;
    int lane = threadIdx.x & 31;

    int beg = g_off[node];
    int end = g_off[node + 1];
    float di = g_dinv[node];
    float self = di * di;

    const float2* hb = (const float2*)g_h;
    float2 acc = ((const float2*)bias)[lane];
    float2 hs = hb[(size_t)node * 32 + lane];
    acc.x += hs.x * self;
    acc.y += hs.y * self;

    int j = beg;
    for (; j + 1 < end; j += 2) {
        int   s0 = g_src[j],     s1 = g_src[j + 1];
        float w0 = g_nrm[j],     w1 = g_nrm[j + 1];
        float2 h0 = hb[(size_t)s0 * 32 + lane];
        float2 h1 = hb[(size_t)s1 * 32 + lane];
        acc.x += h0.x * w0; acc.y += h0.y * w0;
        acc.x += h1.x * w1; acc.y += h1.y * w1;
    }
    if (j < end) {
        int   s0 = g_src[j];
        float w0 = g_nrm[j];
        float2 h0 = hb[(size_t)s0 * 32 + lane];
        acc.x += h0.x * w0; acc.y += h0.y * w0;
    }

    if (do_relu) {
        acc.x = fmaxf(acc.x, 0.f);
        acc.y = fmaxf(acc.y, 0.f);
    }
    ((float2*)(out + (size_t)node * 192 + offc))[lane] = acc;
}

// ---------------- graph embedding: columnwise max into DEVICE scratch ------

__global__ void k_gmax(const float* __restrict__ ne, int n) {
    int j = threadIdx.x;  // 0..191
    float m = -FLT_MAX;
    for (int i = blockIdx.x; i < n; i += gridDim.x)
        m = fmaxf(m, ne[(size_t)i * 192 + j]);
    atomicMaxFloat(&g_gmax[j], m);
}

// ---------------- finalize: copy gmax + target logits (plain stores) -------

__global__ void k_final(const float* __restrict__ ne,
                        const float* __restrict__ fcW,
                        const float* __restrict__ fcb,
                        const int* __restrict__ tgt,
                        float* __restrict__ outtail) {
    int tid = threadIdx.x;  // 192 threads
    outtail[tid] = g_gmax[tid];

    if (tid < 32) {
        int t = tgt[0];
        const float* row = ne + (size_t)t * 192;
        float s0 = 0.f, s1 = 0.f, s2 = 0.f, s3 = 0.f;
        for (int k = tid; k < 192; k += 32) {
            float e = row[k];
            s0 += e * fcW[k * 4 + 0];
            s1 += e * fcW[k * 4 + 1];
            s2 += e * fcW[k * 4 + 2];
            s3 += e * fcW[k * 4 + 3];
        }
        #pragma unroll
        for (int o = 16; o > 0; o >>= 1) {
            s0 += __shfl_down_sync(0xFFFFFFFF, s0, o);
            s1 += __shfl_down_sync(0xFFFFFFFF, s1, o);
            s2 += __shfl_down_sync(0xFFFFFFFF, s2, o);
            s3 += __shfl_down_sync(0xFFFFFFFF, s3, o);
        }
        if (tid == 0) {
            outtail[192 + 0] = s0 + fcb[0];
            outtail[192 + 1] = s1 + fcb[1];
            outtail[192 + 2] = s2 + fcb[2];
            outtail[192 + 3] = s3 + fcb[3];
        }
    }
}

// ---------------- launch ----------------

extern "C" void kernel_launch(void* const* d_in, const int* in_sizes, int n_in,
                              void* d_out, int out_size) {
    const float* x   = (const float*)d_in[0];
    const int*   ei  = (const int*)d_in[1];
    // d_in[2] = batch (unused)
    const int*   tgt = (const int*)d_in[3];
    const float* W1  = (const float*)d_in[4];
    const float* b1  = (const float*)d_in[5];
    const float* W2  = (const float*)d_in[6];
    const float* b2  = (const float*)d_in[7];
    const float* W3  = (const float*)d_in[8];
    const float* b3  = (const float*)d_in[9];
    const float* fcW = (const float*)d_in[10];
    const float* fcb = (const float*)d_in[11];

    float* out = (float*)d_out;

    const int n = in_sizes[0] / 64;   // 50000
    const int E = in_sizes[1] / 2;    // 800000

    const int* srcA = ei;             // edge_index[0]
    const int* dstA = ei + E;         // edge_index[1]

    float* ne = out;                  // [n,192]

    const int B = 256;
    const int nBlkN  = (n + B - 1) / B;
    const int nBlkE  = (E + B - 1) / B;
    const int nBlkG  = (n + 63) / 64;
    const int nBlkW  = (n * 32 + B - 1) / B;          // warp-per-node gather
    const int nChunk = (n + SCAN_CHUNK - 1) / SCAN_CHUNK;  // 49 scan blocks

    // ---- CSR build (shared by all 3 layers) ----
    k_zero<<<nBlkN, B>>>(n);
    k_hist<<<nBlkE, B>>>(dstA, E);
    k_scan1<<<nChunk, B>>>(n);       // local scan + dinv
    k_scan2<<<1, 256>>>(nChunk);     // scan block partials
    k_scan3<<<nChunk, B>>>(n, E);    // propagate + reset cursor
    k_fill<<<nBlkE, B>>>(srcA, dstA, E);

    // ---- layer 1: x (ld 64) -> cols [0,64), relu ----
    k_gemm64<<<nBlkG, B>>>(x, 64, W1, n);
    k_gather<<<nBlkW, B>>>(b1, ne, n, 0, 1);

    // ---- layer 2: x1 = ne[:,0:64) (ld 192) -> cols [64,128), relu ----
    k_gemm64<<<nBlkG, B>>>(ne, 192, W2, n);
    k_gather<<<nBlkW, B>>>(b2, ne, n, 64, 1);

    // ---- layer 3: x2 = ne[:,64:128) (ld 192) -> cols [128,192), no relu ----
    k_gemm64<<<nBlkG, B>>>(ne + 64, 192, W3, n);
    k_gather<<<nBlkW, B>>>(b3, ne, n, 128, 0);

    // ---- graph embedding (device scratch) + tail write ----
    k_gmax<<<512, 192>>>(ne, n);
    k_final<<<1, 192>>>(ne, fcW, fcb, tgt, out + (size_t)n * 192);
}

// round 11
// speedup vs baseline: 1.0080x; 1.0013x over previous
#include <cuda_runtime.h>
#include <cfloat>
#include <cstdint>

// ----------------------------------------------------------------------------
// GnnSynthetic: 3-layer GCN forward, N=50000 nodes, E=800000 edges, dims 64.
// Output layout (fp32): [node_embeddings N x 192][graph_embedding 192][logits 4]
//
// Hard rules learned:
//   R4/R5: no atomics into d_in/d_out (host-coherent buffers trap, err 717).
//   R6:    integer inputs are int32 on device.
//   R7:    single-block scan was 70us (30% of runtime) -> multi-block 3-pass scan.
// ----------------------------------------------------------------------------

#define MAXN 50000
#define MAXE 800000
#define SCAN_CHUNK 1024   // elements per block in the scan passes

__device__ __align__(16) float g_h[(size_t)MAXN * 64];  // GEMM result h = X @ W
__device__ float g_dinv[MAXN];             // rsqrt(deg)
__device__ __align__(16) int g_cnt[MAXN];  // histogram / fill cursor
__device__ __align__(16) int g_off[MAXN + 4]; // CSR row offsets (by dst)
__device__ int   g_src[MAXE];              // CSR column indices (src node)
__device__ float g_nrm[MAXE];              // per-edge norm dinv[src]*dinv[dst]
__device__ float g_gmax[192];              // graph-max accumulator (device-local)
__device__ int   g_bsum[256];              // scan block partials

// ---------------- helpers ----------------

__device__ __forceinline__ void atomicMaxFloat(float* addr, float v) {
    if (v >= 0.0f) atomicMax((int*)addr, __float_as_int(v));
    else           atomicMin((unsigned int*)addr, __float_as_uint(v));
}

// ---------------- CSR build ----------------

__global__ void k_zero(int n) {
    int i = blockIdx.x * blockDim.x + threadIdx.x;
    if (i < n)   g_cnt[i] = 0;
    if (i < 192) g_gmax[i] = -FLT_MAX;
}

__global__ void k_hist(const int* __restrict__ dstA, int E) {
    int e = blockIdx.x * blockDim.x + threadIdx.x;
    if (e < E) atomicAdd(&g_cnt[dstA[e]], 1);
}

// ---- scan pass 1: per-block local exclusive scan (coalesced int4) + dinv ----
// 256 threads, 4 elements/thread, SCAN_CHUNK per block.
__global__ void k_scan1(int n) {
    __shared__ int warpsum[8];
    int tid  = threadIdx.x;
    int lane = tid & 31, wid = tid >> 5;
    int idx  = blockIdx.x * SCAN_CHUNK + tid * 4;

    int4 v = make_int4(0, 0, 0, 0);
    if (idx + 3 < n) {
        v = *(const int4*)(g_cnt + idx);
    } else {
        if (idx + 0 < n) v.x = g_cnt[idx + 0];
        if (idx + 1 < n) v.y = g_cnt[idx + 1];
        if (idx + 2 < n) v.z = g_cnt[idx + 2];
        if (idx + 3 < n) v.w = g_cnt[idx + 3];
    }
    int s = v.x + v.y + v.z + v.w;

    // fold in dinv computation (reads v anyway)
    if (idx + 0 < n) g_dinv[idx + 0] = rsqrtf((float)v.x + 1.0f);
    if (idx + 1 < n) g_dinv[idx + 1] = rsqrtf((float)v.y + 1.0f);
    if (idx + 2 < n) g_dinv[idx + 2] = rsqrtf((float)v.z + 1.0f);
    if (idx + 3 < n) g_dinv[idx + 3] = rsqrtf((float)v.w + 1.0f);

    // warp inclusive scan of s
    int p = s;
    #pragma unroll
    for (int o = 1; o < 32; o <<= 1) {
        int t = __shfl_up_sync(0xFFFFFFFF, p, o);
        if (lane >= o) p += t;
    }
    if (lane == 31) warpsum[wid] = p;
    __syncthreads();
    if (wid == 0) {
        int ws = (lane < 8) ? warpsum[lane] : 0;
        #pragma unroll
        for (int o = 1; o < 8; o <<= 1) {
            int t = __shfl_up_sync(0xFFFFFFFF, ws, o);
            if (lane >= o) ws += t;
        }
        if (lane < 8) warpsum[lane] = ws;
    }
    __syncthreads();

    int excl = ((wid > 0) ? warpsum[wid - 1] : 0) + (p - s);  // thread's exclusive start
    int run = excl;
    if (idx + 0 < n) { g_off[idx + 0] = run; run += v.x; }
    if (idx + 1 < n) { g_off[idx + 1] = run; run += v.y; }
    if (idx + 2 < n) { g_off[idx + 2] = run; run += v.z; }
    if (idx + 3 < n) { g_off[idx + 3] = run; }

    if (tid == 0) g_bsum[blockIdx.x] = warpsum[7];  // block total
}

// ---- scan pass 2: exclusive scan of block partials (single small block) ----
__global__ void k_scan2(int nb) {
    __shared__ int sh[256];
    int tid = threadIdx.x;
    int v = (tid < nb) ? g_bsum[tid] : 0;
    sh[tid] = v;
    __syncthreads();
    #pragma unroll
    for (int o = 1; o < 256; o <<= 1) {
        int t = (tid >= o) ? sh[tid - o] : 0;
        __syncthreads();
        sh[tid] += t;
        __syncthreads();
    }
    if (tid < nb) g_bsum[tid] = sh[tid] - v;  // exclusive
}

// ---- scan pass 3: add block prefix, reset cursor, cap total ----
__global__ void k_scan3(int n, int E) {
    int tid = threadIdx.x;
    int idx = blockIdx.x * SCAN_CHUNK + tid * 4;
    int add = g_bsum[blockIdx.x];
    #pragma unroll
    for (int k = 0; k < 4; k++) {
        int i = idx + k;
        if (i < n) { g_off[i] += add; g_cnt[i] = 0; }
    }
    if (blockIdx.x == 0 && tid == 0) g_off[n] = E;
}

__global__ void k_fill(const int* __restrict__ srcA,
                       const int* __restrict__ dstA, int E) {
    int e = blockIdx.x * blockDim.x + threadIdx.x;
    if (e >= E) return;
    int s = srcA[e];
    int d = dstA[e];
    int pos = atomicAdd(&g_cnt[d], 1);
    int idx = g_off[d] + pos;
    g_src[idx] = s;
    g_nrm[idx] = g_dinv[s] * g_dinv[d];
}

// ---------------- GEMM: g_h[N,64] = X[N,64(ldx)] @ W[64,64] ----------------

__global__ void k_gemm64(const float* __restrict__ X, int ldx,
                         const float* __restrict__ W, int nrows) {
    __shared__ float As[64][65];
    __shared__ float Ws[64][64];

    int tid  = threadIdx.x;
    int row0 = blockIdx.x * 64;

    {
        const float4* W4 = (const float4*)W;
        float4* Ws4 = (float4*)Ws;
        #pragma unroll
        for (int i = tid; i < 1024; i += 256) Ws4[i] = W4[i];
    }
    #pragma unroll
    for (int i = tid; i < 1024; i += 256) {
        int r = i >> 4, c4 = i & 15;
        int grow = row0 + r;
        float4 v = make_float4(0.f, 0.f, 0.f, 0.f);
        if (grow < nrows) v = *(const float4*)(X + (size_t)grow * ldx + c4 * 4);
        As[r][c4 * 4 + 0] = v.x;
        As[r][c4 * 4 + 1] = v.y;
        As[r][c4 * 4 + 2] = v.z;
        As[r][c4 * 4 + 3] = v.w;
    }
    __syncthreads();

    int tx = tid & 15, ty = tid >> 4;
    float acc[4][4];
    #pragma unroll
    for (int i = 0; i < 4; i++)
        #pragma unroll
        for (int j = 0; j < 4; j++) acc[i][j] = 0.f;

    #pragma unroll
    for (int k = 0; k < 64; k++) {
        float4 b = *(const float4*)(&Ws[k][tx * 4]);
        #pragma unroll
        for (int i = 0; i < 4; i++) {
            float a = As[ty * 4 + i][k];
            acc[i][0] += a * b.x;
            acc[i][1] += a * b.y;
            acc[i][2] += a * b.z;
            acc[i][3] += a * b.w;
        }
    }

    #pragma unroll
    for (int i = 0; i < 4; i++) {
        int grow = row0 + ty * 4 + i;
        if (grow < nrows)
            *(float4*)(g_h + (size_t)grow * 64 + tx * 4) =
                make_float4(acc[i][0], acc[i][1], acc[i][2], acc[i][3]);
    }
}

// ---------------- gather: warp per node (plain stores into d_out) ----------

__global__ void k_gather(const float* __restrict__ bias,
                         float* __restrict__ out, int n, int offc, int do_relu) {
    int node = (blockIdx.x * blockDim.x + threadIdx.x) >> 5;
    if (node >= n) return;
    int lane = threadIdx.x & 31;

    int beg = g_off[node];
    int end = g_off[node + 1];
    float di = g_dinv[node];
    float self = di * di;

    const float2* hb = (const float2*)g_h;
    float2 acc = ((const float2*)bias)[lane];
    float2 hs = hb[(size_t)node * 32 + lane];
    acc.x += hs.x * self;
    acc.y += hs.y * self;

    int j = beg;
    for (; j + 1 < end; j += 2) {
        int   s0 = g_src[j],     s1 = g_src[j + 1];
        float w0 = g_nrm[j],     w1 = g_nrm[j + 1];
        float2 h0 = hb[(size_t)s0 * 32 + lane];
        float2 h1 = hb[(size_t)s1 * 32 + lane];
        acc.x += h0.x * w0; acc.y += h0.y * w0;
        acc.x += h1.x * w1; acc.y += h1.y * w1;
    }
    if (j < end) {
        int   s0 = g_src[j];
        float w0 = g_nrm[j];
        float2 h0 = hb[(size_t)s0 * 32 + lane];
        acc.x += h0.x * w0; acc.y += h0.y * w0;
    }

    if (do_relu) {
        acc.x = fmaxf(acc.x, 0.f);
        acc.y = fmaxf(acc.y, 0.f);
    }
    ((float2*)(out + (size_t)node * 192 + offc))[lane] = acc;
}

// ---------------- graph embedding: columnwise max into DEVICE scratch ------

__global__ void k_gmax(const float* __restrict__ ne, int n) {
    int j = threadIdx.x;  // 0..191
    float m = -FLT_MAX;
    for (int i = blockIdx.x; i < n; i += gridDim.x)
        m = fmaxf(m, ne[(size_t)i * 192 + j]);
    atomicMaxFloat(&g_gmax[j], m);
}

// ---------------- finalize: copy gmax + target logits (plain stores) -------

__global__ void k_final(const float* __restrict__ ne,
                        const float* __restrict__ fcW,
                        const float* __restrict__ fcb,
                        const int* __restrict__ tgt,
                        float* __restrict__ outtail) {
    int tid = threadIdx.x;  // 192 threads
    outtail[tid] = g_gmax[tid];

    if (tid < 32) {
        int t = tgt[0];
        const float* row = ne + (size_t)t * 192;
        float s0 = 0.f, s1 = 0.f, s2 = 0.f, s3 = 0.f;
        for (int k = tid; k < 192; k += 32) {
            float e = row[k];
            s0 += e * fcW[k * 4 + 0];
            s1 += e * fcW[k * 4 + 1];
            s2 += e * fcW[k * 4 + 2];
            s3 += e * fcW[k * 4 + 3];
        }
        #pragma unroll
        for (int o = 16; o > 0; o >>= 1) {
            s0 += __shfl_down_sync(0xFFFFFFFF, s0, o);
            s1 += __shfl_down_sync(0xFFFFFFFF, s1, o);
            s2 += __shfl_down_sync(0xFFFFFFFF, s2, o);
            s3 += __shfl_down_sync(0xFFFFFFFF, s3, o);
        }
        if (tid == 0) {
            outtail[192 + 0] = s0 + fcb[0];
            outtail[192 + 1] = s1 + fcb[1];
            outtail[192 + 2] = s2 + fcb[2];
            outtail[192 + 3] = s3 + fcb[3];
        }
    }
}

// ---------------- launch ----------------

extern "C" void kernel_launch(void* const* d_in, const int* in_sizes, int n_in,
                              void* d_out, int out_size) {
    const float* x   = (const float*)d_in[0];
    const int*   ei  = (const int*)d_in[1];
    // d_in[2] = batch (unused)
    const int*   tgt = (const int*)d_in[3];
    const float* W1  = (const float*)d_in[4];
    const float* b1  = (const float*)d_in[5];
    const float* W2  = (const float*)d_in[6];
    const float* b2  = (const float*)d_in[7];
    const float* W3  = (const float*)d_in[8];
    const float* b3  = (const float*)d_in[9];
    const float* fcW = (const float*)d_in[10];
    const float* fcb = (const float*)d_in[11];

    float* out = (float*)d_out;

    const int n = in_sizes[0] / 64;   // 50000
    const int E = in_sizes[1] / 2;    // 800000

    const int* srcA = ei;             // edge_index[0]
    const int* dstA = ei + E;         // edge_index[1]

    float* ne = out;                  // [n,192]

    const int B = 256;
    const int nBlkN  = (n + B - 1) / B;
    const int nBlkE  = (E + B - 1) / B;
    const int nBlkG  = (n + 63) / 64;
    const int nBlkW  = (n * 32 + B - 1) / B;          // warp-per-node gather
    const int nChunk = (n + SCAN_CHUNK - 1) / SCAN_CHUNK;  // 49 scan blocks

    // ---- CSR build (shared by all 3 layers) ----
    k_zero<<<nBlkN, B>>>(n);
    k_hist<<<nBlkE, B>>>(dstA, E);
    k_scan1<<<nChunk, B>>>(n);       // local scan + dinv
    k_scan2<<<1, 256>>>(nChunk);     // scan block partials
    k_scan3<<<nChunk, B>>>(n, E);    // propagate + reset cursor
    k_fill<<<nBlkE, B>>>(srcA, dstA, E);

    // ---- layer 1: x (ld 64) -> cols [0,64), relu ----
    k_gemm64<<<nBlkG, B>>>(x, 64, W1, n);
    k_gather<<<nBlkW, B>>>(b1, ne, n, 0, 1);

    // ---- layer 2: x1 = ne[:,0:64) (ld 192) -> cols [64,128), relu ----
    k_gemm64<<<nBlkG, B>>>(ne, 192, W2, n);
    k_gather<<<nBlkW, B>>>(b2, ne, n, 64, 1);

    // ---- layer 3: x2 = ne[:,64:128) (ld 192) -> cols [128,192), no relu ----
    k_gemm64<<<nBlkG, B>>>(ne + 64, 192, W3, n);
    k_gather<<<nBlkW, B>>>(b3, ne, n, 128, 0);

    // ---- graph embedding (device scratch) + tail write ----
    k_gmax<<<512, 192>>>(ne, n);
    k_final<<<1, 192>>>(ne, fcW, fcb, tgt, out + (size_t)n * 192);
}